// round 3
// baseline (speedup 1.0000x reference)
#include <cuda_runtime.h>
#include <math.h>

#define NTOK   2048
#define DIM    1024
#define NHEADS 16
#define DHEAD  64

// ---------------- scratch (no allocations allowed) ----------------
__device__ float g_xn [NTOK * DIM];
__device__ float g_q  [NTOK * DIM];
__device__ float g_k  [NTOK * DIM];
__device__ float g_v  [NTOK * DIM];
__device__ float g_ktT[NHEADS * DHEAD * NTOK];   // [h][e][n]
__device__ float g_ao [NTOK * DIM];

// ---------------- LayerNorm ----------------
__global__ void ln_kernel(const float* __restrict__ x,
                          const float* __restrict__ gamma,
                          float* __restrict__ xn) {
    __shared__ float red[16];
    const int row = blockIdx.x;
    const float* xr = x + (long)row * DIM;
    float v[4];
    float s = 0.f, ss = 0.f;
#pragma unroll
    for (int i = 0; i < 4; i++) {
        v[i] = xr[threadIdx.x + i * 256];
        s += v[i];
        ss += v[i] * v[i];
    }
#pragma unroll
    for (int o = 16; o > 0; o >>= 1) {
        s  += __shfl_xor_sync(0xffffffffu, s,  o);
        ss += __shfl_xor_sync(0xffffffffu, ss, o);
    }
    if ((threadIdx.x & 31) == 0) {
        red[threadIdx.x >> 5]       = s;
        red[8 + (threadIdx.x >> 5)] = ss;
    }
    __syncthreads();
    s = red[0]; ss = red[8];
#pragma unroll
    for (int i = 1; i < 8; i++) { s += red[i]; ss += red[8 + i]; }
    const float mu  = s * (1.f / DIM);
    const float var = ss * (1.f / DIM) - mu * mu;
    const float inv = rsqrtf(var + 1e-5f);
    float* o = xn + (long)row * DIM;
#pragma unroll
    for (int i = 0; i < 4; i++) {
        const int c = threadIdx.x + i * 256;
        o[c] = (v[i] - mu) * inv * gamma[c];
    }
}

// ---------------- register-tiled SGEMM (row-major NN) ----------------
template <int BM, int BN, int BK, int TM, int TN>
__global__ __launch_bounds__((BM / TM) * (BN / TN))
void sgemm_nn(const float* __restrict__ A, const float* __restrict__ B,
              float* __restrict__ C,
              int M, int N, int K, int lda, int ldb, int ldc) {
    constexpr int THREADS = (BM / TM) * (BN / TN);
    __shared__ __align__(16) float As[BK][BM];
    __shared__ __align__(16) float Bs[BK][BN];

    const int tid  = threadIdx.x;
    const int tx   = tid % (BN / TN);
    const int ty   = tid / (BN / TN);
    const int brow = blockIdx.y * BM;
    const int bcol = blockIdx.x * BN;

    float acc[TM][TN];
#pragma unroll
    for (int i = 0; i < TM; i++)
#pragma unroll
        for (int j = 0; j < TN; j++) acc[i][j] = 0.f;

    constexpr int A_F4 = BM * BK / 4;
    constexpr int B_F4 = BK * BN / 4;

    for (int k0 = 0; k0 < K; k0 += BK) {
#pragma unroll
        for (int p = tid; p < A_F4; p += THREADS) {
            const int row = p / (BK / 4);
            const int kc  = (p % (BK / 4)) * 4;
            const float4 t = *reinterpret_cast<const float4*>(
                A + (long)(brow + row) * lda + k0 + kc);
            As[kc + 0][row] = t.x;
            As[kc + 1][row] = t.y;
            As[kc + 2][row] = t.z;
            As[kc + 3][row] = t.w;
        }
#pragma unroll
        for (int p = tid; p < B_F4; p += THREADS) {
            const int kr = p / (BN / 4);
            const int nc = (p % (BN / 4)) * 4;
            *reinterpret_cast<float4*>(&Bs[kr][nc]) =
                *reinterpret_cast<const float4*>(B + (long)(k0 + kr) * ldb + bcol + nc);
        }
        __syncthreads();
#pragma unroll
        for (int kk = 0; kk < BK; kk++) {
            float a[TM], b[TN];
#pragma unroll
            for (int i = 0; i < TM; i += 4) {
                const float4 t = *reinterpret_cast<const float4*>(&As[kk][ty * TM + i]);
                a[i] = t.x; a[i + 1] = t.y; a[i + 2] = t.z; a[i + 3] = t.w;
            }
#pragma unroll
            for (int j = 0; j < TN; j += 4) {
                const float4 t = *reinterpret_cast<const float4*>(&Bs[kk][tx * TN + j]);
                b[j] = t.x; b[j + 1] = t.y; b[j + 2] = t.z; b[j + 3] = t.w;
            }
#pragma unroll
            for (int i = 0; i < TM; i++)
#pragma unroll
                for (int j = 0; j < TN; j++)
                    acc[i][j] = fmaf(a[i], b[j], acc[i][j]);
        }
        __syncthreads();
    }
#pragma unroll
    for (int i = 0; i < TM; i++) {
#pragma unroll
        for (int j = 0; j < TN; j += 4) {
            float4 t;
            t.x = acc[i][j]; t.y = acc[i][j + 1]; t.z = acc[i][j + 2]; t.w = acc[i][j + 3];
            *reinterpret_cast<float4*>(
                C + (long)(brow + ty * TM + i) * ldc + bcol + tx * TN + j) = t;
        }
    }
}

// ---------------- RoPE (interleaved pairs) + optional scale, in place ----------------
__global__ void rope_kernel(float* __restrict__ t, float scale) {
    const int idx = blockIdx.x * blockDim.x + threadIdx.x;  // over NTOK*512 pairs
    const int row = idx >> 9;
    const int pc  = idx & 511;
    const int c   = pc * 2;          // even column in [0,1024)
    const int d   = c & 63;          // even position within head
    const float pos = (float)row;
    const int f0 = (d < 32) ? d : d - 32;
    const int f1 = (d + 1 < 32) ? d + 1 : d - 31;
    const float th0 = powf(10000.f, -(float)f0 * (1.f / 32.f));
    const float th1 = powf(10000.f, -(float)f1 * (1.f / 32.f));
    const float a0 = pos * th0;
    const float a1 = pos * th1;
    float2* p = reinterpret_cast<float2*>(t + (long)row * DIM + c);
    const float2 xv = *p;
    const float y0 = xv.x * cosf(a0) - xv.y * sinf(a0);
    const float y1 = xv.y * cosf(a1) + xv.x * sinf(a1);
    float2 out;
    out.x = y0 * scale;
    out.y = y1 * scale;
    *p = out;
}

// ---------------- per-head bilinear: ktT[h][e][n] = sum_d k[n, h*64+d] * Wb[h,d,e] ----------------
__global__ void bilinear_kernel(const float* __restrict__ k,
                                const float* __restrict__ Wb,
                                float* __restrict__ ktT) {
    const int h = blockIdx.y;
    const int rowbase = blockIdx.x * 64;
    __shared__ float Wbs[64][64];
    __shared__ float ks[64][65];
    for (int p = threadIdx.x; p < 64 * 64; p += 256) {
        const int r = p / 64, d = p % 64;
        Wbs[r][d] = Wb[h * 4096 + p];
        ks[r][d]  = k[(long)(rowbase + r) * DIM + h * 64 + d];
    }
    __syncthreads();
    for (int p = threadIdx.x; p < 64 * 64; p += 256) {
        const int e = p / 64, r = p % 64;
        float s = 0.f;
#pragma unroll
        for (int d = 0; d < 64; d++) s = fmaf(ks[r][d], Wbs[d][e], s);
        ktT[((long)h * 64 + e) * NTOK + rowbase + r] = s;
    }
}

// ---------------- fused flash attention: sim -> softmax -> @V ----------------
// grid (NTOK/64, NHEADS), 256 threads. Each block: 64 queries of one head.
// Thread (ty,tx): rows 4ty..4ty+3, cols 4tx..4tx+3 (of S / of O's head-dims).
__global__ __launch_bounds__(256)
void flash_kernel(const float* __restrict__ q,
                  const float* __restrict__ ktT,
                  const float* __restrict__ v,
                  float* __restrict__ ao) {
    extern __shared__ float sm[];
    float (*QsT)[64] = (float (*)[64])(sm);            // [e][i]
    float (*KVs)[64] = (float (*)[64])(sm + 4096);     // Ks[e][j] then Vs[j][e]
    float (*Ps)[65]  = (float (*)[65])(sm + 8192);     // [i][j], padded

    const int h     = blockIdx.y;
    const int qbase = blockIdx.x * 64;
    const int tid   = threadIdx.x;
    const int tx    = tid & 15;
    const int ty    = tid >> 4;

    // load Q tile transposed: QsT[e][i]
    for (int p = tid; p < 1024; p += 256) {
        const int i = p >> 4, ec = (p & 15) * 4;
        const float4 t = *reinterpret_cast<const float4*>(
            q + (long)(qbase + i) * DIM + h * 64 + ec);
        QsT[ec + 0][i] = t.x; QsT[ec + 1][i] = t.y;
        QsT[ec + 2][i] = t.z; QsT[ec + 3][i] = t.w;
    }

    float O[4][4];
    float m[4], l[4];
#pragma unroll
    for (int i = 0; i < 4; i++) {
        m[i] = -3.4e38f; l[i] = 0.f;
#pragma unroll
        for (int j = 0; j < 4; j++) O[i][j] = 0.f;
    }
    __syncthreads();

    for (int j0 = 0; j0 < NTOK; j0 += 64) {
        // ---- Ks[e][j] from ktT ----
        for (int p = tid; p < 1024; p += 256) {
            const int e = p >> 4, jc = (p & 15) * 4;
            *reinterpret_cast<float4*>(&KVs[e][jc]) =
                *reinterpret_cast<const float4*>(
                    ktT + ((long)h * 64 + e) * NTOK + j0 + jc);
        }
        __syncthreads();

        // ---- S = Q @ Kt^T  (64x64x64) ----
        float s[4][4];
#pragma unroll
        for (int i = 0; i < 4; i++)
#pragma unroll
            for (int j = 0; j < 4; j++) s[i][j] = 0.f;
        for (int e = 0; e < 64; e++) {
            const float4 aa = *reinterpret_cast<const float4*>(&QsT[e][ty * 4]);
            const float4 bb = *reinterpret_cast<const float4*>(&KVs[e][tx * 4]);
            const float a[4] = {aa.x, aa.y, aa.z, aa.w};
            const float b[4] = {bb.x, bb.y, bb.z, bb.w};
#pragma unroll
            for (int i = 0; i < 4; i++)
#pragma unroll
                for (int j = 0; j < 4; j++)
                    s[i][j] = fmaf(a[i], b[j], s[i][j]);
        }

        // ---- online softmax update ----
#pragma unroll
        for (int i = 0; i < 4; i++) {
            float mm = fmaxf(fmaxf(s[i][0], s[i][1]), fmaxf(s[i][2], s[i][3]));
#pragma unroll
            for (int o = 8; o > 0; o >>= 1)
                mm = fmaxf(mm, __shfl_xor_sync(0xffffffffu, mm, o));
            const float mn   = fmaxf(m[i], mm);
            const float corr = __expf(m[i] - mn);
            m[i] = mn;
            float rs = 0.f;
#pragma unroll
            for (int j = 0; j < 4; j++) {
                s[i][j] = __expf(s[i][j] - mn);
                rs += s[i][j];
            }
#pragma unroll
            for (int o = 8; o > 0; o >>= 1)
                rs += __shfl_xor_sync(0xffffffffu, rs, o);
            l[i] = l[i] * corr + rs;
#pragma unroll
            for (int e = 0; e < 4; e++) O[i][e] *= corr;
#pragma unroll
            for (int j = 0; j < 4; j++) Ps[ty * 4 + i][tx * 4 + j] = s[i][j];
        }
        __syncthreads();

        // ---- Vs[j][e] overwrites Ks ----
        for (int p = tid; p < 1024; p += 256) {
            const int j = p >> 4, ec = (p & 15) * 4;
            *reinterpret_cast<float4*>(&KVs[j][ec]) =
                *reinterpret_cast<const float4*>(
                    v + (long)(j0 + j) * DIM + h * 64 + ec);
        }
        __syncthreads();

        // ---- O += P @ V ----
        for (int jj = 0; jj < 64; jj++) {
            float a[4];
#pragma unroll
            for (int i = 0; i < 4; i++) a[i] = Ps[ty * 4 + i][jj];
            const float4 bb = *reinterpret_cast<const float4*>(&KVs[jj][tx * 4]);
            const float b[4] = {bb.x, bb.y, bb.z, bb.w};
#pragma unroll
            for (int i = 0; i < 4; i++)
#pragma unroll
                for (int e = 0; e < 4; e++)
                    O[i][e] = fmaf(a[i], b[e], O[i][e]);
        }
        __syncthreads();
    }

    // ---- epilogue: normalize, store ----
#pragma unroll
    for (int i = 0; i < 4; i++) {
        const float inv = 1.f / l[i];
        float4 t;
        t.x = O[i][0] * inv; t.y = O[i][1] * inv;
        t.z = O[i][2] * inv; t.w = O[i][3] * inv;
        *reinterpret_cast<float4*>(
            ao + (long)(qbase + ty * 4 + i) * DIM + h * 64 + tx * 4) = t;
    }
}

// ---------------- launch ----------------
extern "C" void kernel_launch(void* const* d_in, const int* in_sizes, int n_in,
                              void* d_out, int out_size) {
    const float* x     = (const float*)d_in[0];
    const float* gamma = (const float*)d_in[1];
    const float* Wq    = (const float*)d_in[2];
    const float* Wkv   = (const float*)d_in[3];
    const float* Wb    = (const float*)d_in[4];
    const float* Wo    = (const float*)d_in[5];
    float* out = (float*)d_out;

    float *xn, *q, *k, *v, *ktT, *ao;
    cudaGetSymbolAddress((void**)&xn,  g_xn);
    cudaGetSymbolAddress((void**)&q,   g_q);
    cudaGetSymbolAddress((void**)&k,   g_k);
    cudaGetSymbolAddress((void**)&v,   g_v);
    cudaGetSymbolAddress((void**)&ktT, g_ktT);
    cudaGetSymbolAddress((void**)&ao,  g_ao);

    // 1. LayerNorm
    ln_kernel<<<NTOK, 256>>>(x, gamma, xn);

    // 2. q = xn @ Wq ; k = xn @ Wkv[:, :1024] ; v = xn @ Wkv[:, 1024:]
    {
        dim3 g(DIM / 128, NTOK / 128, 1);
        sgemm_nn<128, 128, 16, 8, 8><<<g, 256>>>(xn, Wq, q,
            NTOK, DIM, DIM, DIM, DIM, DIM);
        sgemm_nn<128, 128, 16, 8, 8><<<g, 256>>>(xn, Wkv, k,
            NTOK, DIM, DIM, DIM, 2 * DIM, DIM);
        sgemm_nn<128, 128, 16, 8, 8><<<g, 256>>>(xn, Wkv + DIM, v,
            NTOK, DIM, DIM, DIM, 2 * DIM, DIM);
    }

    // 3. RoPE (+ 1/sqrt(DHEAD) folded into q)
    rope_kernel<<<NTOK * 512 / 256, 256>>>(q, 0.125f);
    rope_kernel<<<NTOK * 512 / 256, 256>>>(k, 1.0f);

    // 4. bilinear K transform -> ktT [h][e][n]
    bilinear_kernel<<<dim3(NTOK / 64, NHEADS), 256>>>(k, Wb, ktT);

    // 5-7. fused attention (QK^T + online softmax + @V)
    {
        const int smem = (4096 + 4096 + 64 * 65) * (int)sizeof(float);  // 49408
        cudaFuncSetAttribute(flash_kernel,
                             cudaFuncAttributeMaxDynamicSharedMemorySize, smem);
        flash_kernel<<<dim3(NTOK / 64, NHEADS), 256, smem>>>(q, ktT, v, ao);
    }

    // 8. out = ao @ Wo
    {
        dim3 g(DIM / 128, NTOK / 128, 1);
        sgemm_nn<128, 128, 16, 8, 8><<<g, 256>>>(ao, Wo, out,
            NTOK, DIM, DIM, DIM, DIM, DIM);
    }
}

// round 5
// speedup vs baseline: 1.3621x; 1.3621x over previous
#include <cuda_runtime.h>
#include <cuda_bf16.h>
#include <math.h>
#include <stdint.h>

#define NTOK   2048
#define DIM    1024
#define NHEADS 16
#define DHEAD  64
#define QKV_LD 3072

// ---------------- scratch (no allocations allowed) ----------------
__device__ float g_xn  [NTOK * DIM];
__device__ float g_qkv [NTOK * QKV_LD];          // q | k | v
__device__ float g_ktT [NHEADS * DHEAD * NTOK];  // [h][e][n]
__device__ float g_ao  [NTOK * DIM];

static __device__ __forceinline__ uint32_t s2u(const void* p) {
    return (uint32_t)__cvta_generic_to_shared(p);
}

#define LDSM4(R, addr) \
    asm volatile("ldmatrix.sync.aligned.m8n8.x4.shared.b16 {%0,%1,%2,%3},[%4];" \
        : "=r"((R)[0]), "=r"((R)[1]), "=r"((R)[2]), "=r"((R)[3]) : "r"(addr))
#define LDSM4T(R, addr) \
    asm volatile("ldmatrix.sync.aligned.m8n8.x4.trans.shared.b16 {%0,%1,%2,%3},[%4];" \
        : "=r"((R)[0]), "=r"((R)[1]), "=r"((R)[2]), "=r"((R)[3]) : "r"(addr))
#define MMA_BF16(D, A, B) \
    asm volatile("mma.sync.aligned.m16n8k16.row.col.f32.bf16.bf16.f32 " \
        "{%0,%1,%2,%3},{%4,%5,%6,%7},{%8,%9},{%0,%1,%2,%3};" \
        : "+f"((D)[0]), "+f"((D)[1]), "+f"((D)[2]), "+f"((D)[3]) \
        : "r"((A)[0]), "r"((A)[1]), "r"((A)[2]), "r"((A)[3]), "r"((B)[0]), "r"((B)[1]))

// ---------------- LayerNorm ----------------
__global__ void ln_kernel(const float* __restrict__ x,
                          const float* __restrict__ gamma,
                          float* __restrict__ xn) {
    __shared__ float red[16];
    const int row = blockIdx.x;
    const float* xr = x + (long)row * DIM;
    float v[4];
    float s = 0.f, ss = 0.f;
#pragma unroll
    for (int i = 0; i < 4; i++) {
        v[i] = xr[threadIdx.x + i * 256];
        s += v[i];
        ss += v[i] * v[i];
    }
#pragma unroll
    for (int o = 16; o > 0; o >>= 1) {
        s  += __shfl_xor_sync(0xffffffffu, s,  o);
        ss += __shfl_xor_sync(0xffffffffu, ss, o);
    }
    if ((threadIdx.x & 31) == 0) {
        red[threadIdx.x >> 5]       = s;
        red[8 + (threadIdx.x >> 5)] = ss;
    }
    __syncthreads();
    s = red[0]; ss = red[8];
#pragma unroll
    for (int i = 1; i < 8; i++) { s += red[i]; ss += red[8 + i]; }
    const float mu  = s * (1.f / DIM);
    const float var = ss * (1.f / DIM) - mu * mu;
    const float inv = rsqrtf(var + 1e-5f);
    float* o = xn + (long)row * DIM;
#pragma unroll
    for (int i = 0; i < 4; i++) {
        const int c = threadIdx.x + i * 256;
        o[c] = (v[i] - mu) * inv * gamma[c];
    }
}

// ---------------- split-bf16 (3-product) tensor-core GEMM ----------------
// C[M x N] = A[M x K] @ B[K x N], fp32 in/out, bf16 hi+lo split, fp32 accum.
// B selected per block column: bcol < ncut -> B0 (ldb0), else B1+(bcol-ncut) (ldb1).
// Block 128x128, BK=32, 8 warps (2x4), warp tile 64x32.
__global__ __launch_bounds__(256)
void gemm_bf16x3(const float* __restrict__ A,
                 const float* __restrict__ B0,
                 const float* __restrict__ B1,
                 float* __restrict__ C,
                 int K, int lda, int ldb0, int ldb1, int ldc, int ncut) {
    __shared__ __align__(16) __nv_bfloat16 As_hi[128][40];   // pad: 80B row stride
    __shared__ __align__(16) __nv_bfloat16 As_lo[128][40];
    __shared__ __align__(16) __nv_bfloat16 Bs_hi[32][136];   // pad: 272B row stride
    __shared__ __align__(16) __nv_bfloat16 Bs_lo[32][136];

    const int tid  = threadIdx.x;
    const int lane = tid & 31;
    const int wid  = tid >> 5;
    const int wm   = wid >> 2;   // 0..1
    const int wn   = wid & 3;    // 0..3
    const int brow = blockIdx.y * 128;
    const int bcol = blockIdx.x * 128;

    const float* Bp;
    int ldb;
    if (bcol < ncut) { Bp = B0 + bcol;          ldb = ldb0; }
    else             { Bp = B1 + (bcol - ncut); ldb = ldb1; }

    float d[4][4][4];
#pragma unroll
    for (int i = 0; i < 4; i++)
#pragma unroll
        for (int j = 0; j < 4; j++)
#pragma unroll
            for (int r = 0; r < 4; r++) d[i][j][r] = 0.f;

    float4 ra[4], rb[4];

    // prefetch tile 0
#pragma unroll
    for (int t = 0; t < 4; t++) {
        const int slot = tid + t * 256;
        const int r1 = slot >> 3, c1 = (slot & 7) * 4;       // A: 128 x 32
        ra[t] = *reinterpret_cast<const float4*>(A + (long)(brow + r1) * lda + c1);
        const int r2 = slot >> 5, c2 = (slot & 31) * 4;      // B: 32 x 128
        rb[t] = *reinterpret_cast<const float4*>(Bp + (long)r2 * ldb + c2);
    }

    const int niter = K / 32;
    for (int kt = 0; kt < niter; kt++) {
        __syncthreads();
        // store staged regs -> smem with hi/lo split
#pragma unroll
        for (int t = 0; t < 4; t++) {
            const int slot = tid + t * 256;
            {
                const int r = slot >> 3, c = (slot & 7) * 4;
                const float vv[4] = {ra[t].x, ra[t].y, ra[t].z, ra[t].w};
#pragma unroll
                for (int j = 0; j < 4; j++) {
                    const __nv_bfloat16 h = __float2bfloat16_rn(vv[j]);
                    As_hi[r][c + j] = h;
                    As_lo[r][c + j] = __float2bfloat16_rn(vv[j] - __bfloat162float(h));
                }
            }
            {
                const int r = slot >> 5, c = (slot & 31) * 4;
                const float vv[4] = {rb[t].x, rb[t].y, rb[t].z, rb[t].w};
#pragma unroll
                for (int j = 0; j < 4; j++) {
                    const __nv_bfloat16 h = __float2bfloat16_rn(vv[j]);
                    Bs_hi[r][c + j] = h;
                    Bs_lo[r][c + j] = __float2bfloat16_rn(vv[j] - __bfloat162float(h));
                }
            }
        }
        __syncthreads();

        // prefetch next tile
        if (kt + 1 < niter) {
            const int k0 = (kt + 1) * 32;
#pragma unroll
            for (int t = 0; t < 4; t++) {
                const int slot = tid + t * 256;
                const int r1 = slot >> 3, c1 = (slot & 7) * 4;
                ra[t] = *reinterpret_cast<const float4*>(
                    A + (long)(brow + r1) * lda + k0 + c1);
                const int r2 = slot >> 5, c2 = (slot & 31) * 4;
                rb[t] = *reinterpret_cast<const float4*>(
                    Bp + (long)(k0 + r2) * ldb + c2);
            }
        }

        // compute on current smem tile
#pragma unroll
        for (int kk = 0; kk < 32; kk += 16) {
            uint32_t a_hi[4][4], a_lo[4][4], b_hi[2][4], b_lo[2][4];
            const int g  = lane >> 3;
            const int ri = lane & 7;
#pragma unroll
            for (int mi = 0; mi < 4; mi++) {
                const int row   = wm * 64 + mi * 16 + (g & 1) * 8 + ri;
                const int chunk = (kk >> 3) + (g >> 1);
                uint32_t addr = s2u(&As_hi[0][0]) + row * 80 + chunk * 16;
                LDSM4(a_hi[mi], addr);
                addr = s2u(&As_lo[0][0]) + row * 80 + chunk * 16;
                LDSM4(a_lo[mi], addr);
            }
#pragma unroll
            for (int nj2 = 0; nj2 < 2; nj2++) {
                const int krow = kk + (g & 1) * 8 + ri;
                const int col  = wn * 32 + nj2 * 16 + (g >> 1) * 8;
                uint32_t addr = s2u(&Bs_hi[0][0]) + krow * 272 + col * 2;
                LDSM4T(b_hi[nj2], addr);
                addr = s2u(&Bs_lo[0][0]) + krow * 272 + col * 2;
                LDSM4T(b_lo[nj2], addr);
            }
#pragma unroll
            for (int mi = 0; mi < 4; mi++)
#pragma unroll
                for (int nj = 0; nj < 4; nj++) {
                    const int nj2 = nj >> 1, u = (nj & 1) * 2;
                    MMA_BF16(d[mi][nj], a_hi[mi], b_hi[nj2] + u);
                    MMA_BF16(d[mi][nj], a_hi[mi], b_lo[nj2] + u);
                    MMA_BF16(d[mi][nj], a_lo[mi], b_hi[nj2] + u);
                }
        }
    }

    // epilogue
#pragma unroll
    for (int mi = 0; mi < 4; mi++)
#pragma unroll
        for (int nj = 0; nj < 4; nj++) {
            const int r  = brow + wm * 64 + mi * 16 + (lane >> 2);
            const int cc = bcol + wn * 32 + nj * 8 + (lane & 3) * 2;
            float2 t0, t1;
            t0.x = d[mi][nj][0]; t0.y = d[mi][nj][1];
            t1.x = d[mi][nj][2]; t1.y = d[mi][nj][3];
            *reinterpret_cast<float2*>(C + (long)r * ldc + cc)       = t0;
            *reinterpret_cast<float2*>(C + (long)(r + 8) * ldc + cc) = t1;
        }
}

// ---------------- RoPE (interleaved pairs) + optional scale, in place ----------------
__global__ void rope_kernel(float* __restrict__ t, int ld, float scale) {
    const int idx = blockIdx.x * blockDim.x + threadIdx.x;  // over NTOK*512 pairs
    const int row = idx >> 9;
    const int pc  = idx & 511;
    const int c   = pc * 2;          // even column in [0,1024)
    const int dd  = c & 63;          // even position within head
    const float pos = (float)row;
    const int f0 = (dd < 32) ? dd : dd - 32;
    const int f1 = (dd + 1 < 32) ? dd + 1 : dd - 31;
    const float th0 = powf(10000.f, -(float)f0 * (1.f / 32.f));
    const float th1 = powf(10000.f, -(float)f1 * (1.f / 32.f));
    const float a0 = pos * th0;
    const float a1 = pos * th1;
    float2* p = reinterpret_cast<float2*>(t + (long)row * ld + c);
    const float2 xv = *p;
    const float y0 = xv.x * cosf(a0) - xv.y * sinf(a0);
    const float y1 = xv.y * cosf(a1) + xv.x * sinf(a1);
    float2 out;
    out.x = y0 * scale;
    out.y = y1 * scale;
    *p = out;
}

// ---------------- per-head bilinear: ktT[h][e][n] = sum_d k[n, h*64+d] * Wb[h,d,e] ----------------
__global__ void bilinear_kernel(const float* __restrict__ k, int ldk,
                                const float* __restrict__ Wb,
                                float* __restrict__ ktT) {
    const int h = blockIdx.y;
    const int rowbase = blockIdx.x * 64;
    __shared__ float Wbs[64][64];
    __shared__ float ks[64][65];
    for (int p = threadIdx.x; p < 64 * 64; p += 256) {
        const int r = p / 64, dd = p % 64;
        Wbs[r][dd] = Wb[h * 4096 + p];
        ks[r][dd]  = k[(long)(rowbase + r) * ldk + h * 64 + dd];
    }
    __syncthreads();
    for (int p = threadIdx.x; p < 64 * 64; p += 256) {
        const int e = p / 64, r = p % 64;
        float s = 0.f;
#pragma unroll
        for (int dd = 0; dd < 64; dd++) s = fmaf(ks[r][dd], Wbs[dd][e], s);
        ktT[((long)h * 64 + e) * NTOK + rowbase + r] = s;
    }
}

// ---------------- fused flash attention: sim -> softmax -> @V ----------------
__global__ __launch_bounds__(256)
void flash_kernel(const float* __restrict__ q, int ldq,
                  const float* __restrict__ ktT,
                  const float* __restrict__ v, int ldv,
                  float* __restrict__ ao) {
    extern __shared__ float sm[];
    float (*QsT)[64] = (float (*)[64])(sm);            // [e][i]
    float (*KVs)[64] = (float (*)[64])(sm + 4096);     // Ks[e][j] then Vs[j][e]
    float (*Ps)[65]  = (float (*)[65])(sm + 8192);     // [i][j], padded

    const int h     = blockIdx.y;
    const int qbase = blockIdx.x * 64;
    const int tid   = threadIdx.x;
    const int tx    = tid & 15;
    const int ty    = tid >> 4;

    for (int p = tid; p < 1024; p += 256) {
        const int i = p >> 4, ec = (p & 15) * 4;
        const float4 t = *reinterpret_cast<const float4*>(
            q + (long)(qbase + i) * ldq + h * 64 + ec);
        QsT[ec + 0][i] = t.x; QsT[ec + 1][i] = t.y;
        QsT[ec + 2][i] = t.z; QsT[ec + 3][i] = t.w;
    }

    float O[4][4];
    float m[4], l[4];
#pragma unroll
    for (int i = 0; i < 4; i++) {
        m[i] = -3.4e38f; l[i] = 0.f;
#pragma unroll
        for (int j = 0; j < 4; j++) O[i][j] = 0.f;
    }
    __syncthreads();

    for (int j0 = 0; j0 < NTOK; j0 += 64) {
        for (int p = tid; p < 1024; p += 256) {
            const int e = p >> 4, jc = (p & 15) * 4;
            *reinterpret_cast<float4*>(&KVs[e][jc]) =
                *reinterpret_cast<const float4*>(
                    ktT + ((long)h * 64 + e) * NTOK + j0 + jc);
        }
        __syncthreads();

        float s[4][4];
#pragma unroll
        for (int i = 0; i < 4; i++)
#pragma unroll
            for (int j = 0; j < 4; j++) s[i][j] = 0.f;
        for (int e = 0; e < 64; e++) {
            const float4 aa = *reinterpret_cast<const float4*>(&QsT[e][ty * 4]);
            const float4 bb = *reinterpret_cast<const float4*>(&KVs[e][tx * 4]);
            const float a[4] = {aa.x, aa.y, aa.z, aa.w};
            const float b[4] = {bb.x, bb.y, bb.z, bb.w};
#pragma unroll
            for (int i = 0; i < 4; i++)
#pragma unroll
                for (int j = 0; j < 4; j++)
                    s[i][j] = fmaf(a[i], b[j], s[i][j]);
        }

#pragma unroll
        for (int i = 0; i < 4; i++) {
            float mm = fmaxf(fmaxf(s[i][0], s[i][1]), fmaxf(s[i][2], s[i][3]));
#pragma unroll
            for (int o = 8; o > 0; o >>= 1)
                mm = fmaxf(mm, __shfl_xor_sync(0xffffffffu, mm, o));
            const float mn   = fmaxf(m[i], mm);
            const float corr = __expf(m[i] - mn);
            m[i] = mn;
            float rs = 0.f;
#pragma unroll
            for (int j = 0; j < 4; j++) {
                s[i][j] = __expf(s[i][j] - mn);
                rs += s[i][j];
            }
#pragma unroll
            for (int o = 8; o > 0; o >>= 1)
                rs += __shfl_xor_sync(0xffffffffu, rs, o);
            l[i] = l[i] * corr + rs;
#pragma unroll
            for (int e = 0; e < 4; e++) O[i][e] *= corr;
#pragma unroll
            for (int j = 0; j < 4; j++) Ps[ty * 4 + i][tx * 4 + j] = s[i][j];
        }
        __syncthreads();

        for (int p = tid; p < 1024; p += 256) {
            const int j = p >> 4, ec = (p & 15) * 4;
            *reinterpret_cast<float4*>(&KVs[j][ec]) =
                *reinterpret_cast<const float4*>(
                    v + (long)(j0 + j) * ldv + h * 64 + ec);
        }
        __syncthreads();

        for (int jj = 0; jj < 64; jj++) {
            float a[4];
#pragma unroll
            for (int i = 0; i < 4; i++) a[i] = Ps[ty * 4 + i][jj];
            const float4 bb = *reinterpret_cast<const float4*>(&KVs[jj][tx * 4]);
            const float b[4] = {bb.x, bb.y, bb.z, bb.w};
#pragma unroll
            for (int i = 0; i < 4; i++)
#pragma unroll
                for (int e = 0; e < 4; e++)
                    O[i][e] = fmaf(a[i], b[e], O[i][e]);
        }
        __syncthreads();
    }

#pragma unroll
    for (int i = 0; i < 4; i++) {
        const float inv = 1.f / l[i];
        float4 t;
        t.x = O[i][0] * inv; t.y = O[i][1] * inv;
        t.z = O[i][2] * inv; t.w = O[i][3] * inv;
        *reinterpret_cast<float4*>(
            ao + (long)(qbase + ty * 4 + i) * DIM + h * 64 + tx * 4) = t;
    }
}

// ---------------- launch ----------------
extern "C" void kernel_launch(void* const* d_in, const int* in_sizes, int n_in,
                              void* d_out, int out_size) {
    const float* x     = (const float*)d_in[0];
    const float* gamma = (const float*)d_in[1];
    const float* Wq    = (const float*)d_in[2];
    const float* Wkv   = (const float*)d_in[3];
    const float* Wb    = (const float*)d_in[4];
    const float* Wo    = (const float*)d_in[5];
    float* out = (float*)d_out;

    float *xn, *qkv, *ktT, *ao;
    cudaGetSymbolAddress((void**)&xn,  g_xn);
    cudaGetSymbolAddress((void**)&qkv, g_qkv);
    cudaGetSymbolAddress((void**)&ktT, g_ktT);
    cudaGetSymbolAddress((void**)&ao,  g_ao);

    float* q = qkv;             // cols [0,1024)
    float* k = qkv + DIM;       // cols [1024,2048)
    float* v = qkv + 2 * DIM;   // cols [2048,3072)

    // 1. LayerNorm
    ln_kernel<<<NTOK, 256>>>(x, gamma, xn);

    // 2. qkv = xn @ [Wq | Wkv]   (one tensor-core GEMM, N=3072)
    {
        dim3 g(QKV_LD / 128, NTOK / 128, 1);
        gemm_bf16x3<<<g, 256>>>(xn, Wq, Wkv, qkv,
                                DIM, DIM, DIM, 2 * DIM, QKV_LD, DIM);
    }

    // 3. RoPE (+ 1/sqrt(DHEAD) folded into q)
    rope_kernel<<<NTOK * 512 / 256, 256>>>(q, QKV_LD, 0.125f);
    rope_kernel<<<NTOK * 512 / 256, 256>>>(k, QKV_LD, 1.0f);

    // 4. bilinear K transform -> ktT [h][e][n]
    bilinear_kernel<<<dim3(NTOK / 64, NHEADS), 256>>>(k, QKV_LD, Wb, ktT);

    // 5-7. fused attention (QK^T + online softmax + @V)
    {
        const int smem = (4096 + 4096 + 64 * 65) * (int)sizeof(float);  // 49408
        cudaFuncSetAttribute(flash_kernel,
                             cudaFuncAttributeMaxDynamicSharedMemorySize, smem);
        flash_kernel<<<dim3(NTOK / 64, NHEADS), 256, smem>>>(
            q, QKV_LD, ktT, v, QKV_LD, ao);
    }

    // 8. out = ao @ Wo   (tensor-core GEMM)
    {
        dim3 g(DIM / 128, NTOK / 128, 1);
        gemm_bf16x3<<<g, 256>>>(ao, Wo, Wo, out,
                                DIM, DIM, DIM, DIM, DIM, 1 << 30);
    }
}

// round 6
// speedup vs baseline: 2.2798x; 1.6738x over previous
#include <cuda_runtime.h>
#include <cuda_bf16.h>
#include <math.h>
#include <stdint.h>

#define NTOK   2048
#define DIM    1024
#define NHEADS 16
#define DHEAD  64
#define QKV_LD 3072

// ---------------- scratch (no allocations allowed) ----------------
__device__ float g_xn  [NTOK * DIM];
__device__ float g_qkv [NTOK * QKV_LD];          // q | k | v (fp32)
__device__ float g_ao  [NTOK * DIM];
__device__ __nv_bfloat16 g_q_hi [NTOK * DIM];    // rotated+scaled q, split
__device__ __nv_bfloat16 g_q_lo [NTOK * DIM];
__device__ __nv_bfloat16 g_kt_hi[NHEADS * DHEAD * NTOK];  // [h][e][n]
__device__ __nv_bfloat16 g_kt_lo[NHEADS * DHEAD * NTOK];
__device__ __nv_bfloat16 g_v_hi [NTOK * DIM];
__device__ __nv_bfloat16 g_v_lo [NTOK * DIM];

static __device__ __forceinline__ uint32_t s2u(const void* p) {
    return (uint32_t)__cvta_generic_to_shared(p);
}

#define LDSM4(R, addr) \
    asm volatile("ldmatrix.sync.aligned.m8n8.x4.shared.b16 {%0,%1,%2,%3},[%4];" \
        : "=r"((R)[0]), "=r"((R)[1]), "=r"((R)[2]), "=r"((R)[3]) : "r"(addr))
#define LDSM4T(R, addr) \
    asm volatile("ldmatrix.sync.aligned.m8n8.x4.trans.shared.b16 {%0,%1,%2,%3},[%4];" \
        : "=r"((R)[0]), "=r"((R)[1]), "=r"((R)[2]), "=r"((R)[3]) : "r"(addr))
#define MMA_BF16(D, A, B) \
    asm volatile("mma.sync.aligned.m16n8k16.row.col.f32.bf16.bf16.f32 " \
        "{%0,%1,%2,%3},{%4,%5,%6,%7},{%8,%9},{%0,%1,%2,%3};" \
        : "+f"((D)[0]), "+f"((D)[1]), "+f"((D)[2]), "+f"((D)[3]) \
        : "r"((A)[0]), "r"((A)[1]), "r"((A)[2]), "r"((A)[3]), "r"((B)[0]), "r"((B)[1]))

static __device__ __forceinline__ void split2(float x, float y,
                                              uint32_t& hi, uint32_t& lo) {
    float2 f; f.x = x; f.y = y;
    __nv_bfloat162 h = __float22bfloat162_rn(f);
    float2 hf = __bfloat1622float2(h);
    float2 r; r.x = x - hf.x; r.y = y - hf.y;
    __nv_bfloat162 l = __float22bfloat162_rn(r);
    hi = *(uint32_t*)&h; lo = *(uint32_t*)&l;
}

// ---------------- LayerNorm ----------------
__global__ void ln_kernel(const float* __restrict__ x,
                          const float* __restrict__ gamma,
                          float* __restrict__ xn) {
    __shared__ float red[16];
    const int row = blockIdx.x;
    const float* xr = x + (long)row * DIM;
    float v[4];
    float s = 0.f, ss = 0.f;
#pragma unroll
    for (int i = 0; i < 4; i++) {
        v[i] = xr[threadIdx.x + i * 256];
        s += v[i];
        ss += v[i] * v[i];
    }
#pragma unroll
    for (int o = 16; o > 0; o >>= 1) {
        s  += __shfl_xor_sync(0xffffffffu, s,  o);
        ss += __shfl_xor_sync(0xffffffffu, ss, o);
    }
    if ((threadIdx.x & 31) == 0) {
        red[threadIdx.x >> 5]       = s;
        red[8 + (threadIdx.x >> 5)] = ss;
    }
    __syncthreads();
    s = red[0]; ss = red[8];
#pragma unroll
    for (int i = 1; i < 8; i++) { s += red[i]; ss += red[8 + i]; }
    const float mu  = s * (1.f / DIM);
    const float var = ss * (1.f / DIM) - mu * mu;
    const float inv = rsqrtf(var + 1e-5f);
    float* o = xn + (long)row * DIM;
#pragma unroll
    for (int i = 0; i < 4; i++) {
        const int c = threadIdx.x + i * 256;
        o[c] = (v[i] - mu) * inv * gamma[c];
    }
}

// ---------------- split-bf16 (3-product) tensor-core GEMM ----------------
__global__ __launch_bounds__(256)
void gemm_bf16x3(const float* __restrict__ A,
                 const float* __restrict__ B0,
                 const float* __restrict__ B1,
                 float* __restrict__ C,
                 int K, int lda, int ldb0, int ldb1, int ldc, int ncut) {
    __shared__ __align__(16) __nv_bfloat16 As_hi[128][40];
    __shared__ __align__(16) __nv_bfloat16 As_lo[128][40];
    __shared__ __align__(16) __nv_bfloat16 Bs_hi[32][136];
    __shared__ __align__(16) __nv_bfloat16 Bs_lo[32][136];

    const int tid  = threadIdx.x;
    const int lane = tid & 31;
    const int wid  = tid >> 5;
    const int wm   = wid >> 2;
    const int wn   = wid & 3;
    const int brow = blockIdx.y * 128;
    const int bcol = blockIdx.x * 128;

    const float* Bp;
    int ldb;
    if (bcol < ncut) { Bp = B0 + bcol;          ldb = ldb0; }
    else             { Bp = B1 + (bcol - ncut); ldb = ldb1; }

    float d[4][4][4];
#pragma unroll
    for (int i = 0; i < 4; i++)
#pragma unroll
        for (int j = 0; j < 4; j++)
#pragma unroll
            for (int r = 0; r < 4; r++) d[i][j][r] = 0.f;

    float4 ra[4], rb[4];
#pragma unroll
    for (int t = 0; t < 4; t++) {
        const int slot = tid + t * 256;
        const int r1 = slot >> 3, c1 = (slot & 7) * 4;
        ra[t] = *reinterpret_cast<const float4*>(A + (long)(brow + r1) * lda + c1);
        const int r2 = slot >> 5, c2 = (slot & 31) * 4;
        rb[t] = *reinterpret_cast<const float4*>(Bp + (long)r2 * ldb + c2);
    }

    const int niter = K / 32;
    for (int kt = 0; kt < niter; kt++) {
        __syncthreads();
#pragma unroll
        for (int t = 0; t < 4; t++) {
            const int slot = tid + t * 256;
            {
                const int r = slot >> 3, c = (slot & 7) * 4;
                const float vv[4] = {ra[t].x, ra[t].y, ra[t].z, ra[t].w};
#pragma unroll
                for (int j = 0; j < 4; j++) {
                    const __nv_bfloat16 h = __float2bfloat16_rn(vv[j]);
                    As_hi[r][c + j] = h;
                    As_lo[r][c + j] = __float2bfloat16_rn(vv[j] - __bfloat162float(h));
                }
            }
            {
                const int r = slot >> 5, c = (slot & 31) * 4;
                const float vv[4] = {rb[t].x, rb[t].y, rb[t].z, rb[t].w};
#pragma unroll
                for (int j = 0; j < 4; j++) {
                    const __nv_bfloat16 h = __float2bfloat16_rn(vv[j]);
                    Bs_hi[r][c + j] = h;
                    Bs_lo[r][c + j] = __float2bfloat16_rn(vv[j] - __bfloat162float(h));
                }
            }
        }
        __syncthreads();

        if (kt + 1 < niter) {
            const int k0 = (kt + 1) * 32;
#pragma unroll
            for (int t = 0; t < 4; t++) {
                const int slot = tid + t * 256;
                const int r1 = slot >> 3, c1 = (slot & 7) * 4;
                ra[t] = *reinterpret_cast<const float4*>(
                    A + (long)(brow + r1) * lda + k0 + c1);
                const int r2 = slot >> 5, c2 = (slot & 31) * 4;
                rb[t] = *reinterpret_cast<const float4*>(
                    Bp + (long)(k0 + r2) * ldb + c2);
            }
        }

#pragma unroll
        for (int kk = 0; kk < 32; kk += 16) {
            uint32_t a_hi[4][4], a_lo[4][4], b_hi[2][4], b_lo[2][4];
            const int g  = lane >> 3;
            const int ri = lane & 7;
#pragma unroll
            for (int mi = 0; mi < 4; mi++) {
                const int row   = wm * 64 + mi * 16 + (g & 1) * 8 + ri;
                const int chunk = (kk >> 3) + (g >> 1);
                uint32_t addr = s2u(&As_hi[0][0]) + row * 80 + chunk * 16;
                LDSM4(a_hi[mi], addr);
                addr = s2u(&As_lo[0][0]) + row * 80 + chunk * 16;
                LDSM4(a_lo[mi], addr);
            }
#pragma unroll
            for (int nj2 = 0; nj2 < 2; nj2++) {
                const int krow = kk + (g & 1) * 8 + ri;
                const int col  = wn * 32 + nj2 * 16 + (g >> 1) * 8;
                uint32_t addr = s2u(&Bs_hi[0][0]) + krow * 272 + col * 2;
                LDSM4T(b_hi[nj2], addr);
                addr = s2u(&Bs_lo[0][0]) + krow * 272 + col * 2;
                LDSM4T(b_lo[nj2], addr);
            }
#pragma unroll
            for (int mi = 0; mi < 4; mi++)
#pragma unroll
                for (int nj = 0; nj < 4; nj++) {
                    const int nj2 = nj >> 1, u = (nj & 1) * 2;
                    MMA_BF16(d[mi][nj], a_hi[mi], b_hi[nj2] + u);
                    MMA_BF16(d[mi][nj], a_hi[mi], b_lo[nj2] + u);
                    MMA_BF16(d[mi][nj], a_lo[mi], b_hi[nj2] + u);
                }
        }
    }

#pragma unroll
    for (int mi = 0; mi < 4; mi++)
#pragma unroll
        for (int nj = 0; nj < 4; nj++) {
            const int r  = brow + wm * 64 + mi * 16 + (lane >> 2);
            const int cc = bcol + wn * 32 + nj * 8 + (lane & 3) * 2;
            float2 t0, t1;
            t0.x = d[mi][nj][0]; t0.y = d[mi][nj][1];
            t1.x = d[mi][nj][2]; t1.y = d[mi][nj][3];
            *reinterpret_cast<float2*>(C + (long)r * ldc + cc)       = t0;
            *reinterpret_cast<float2*>(C + (long)(r + 8) * ldc + cc) = t1;
        }
}

// ---------------- RoPE variants ----------------
__device__ __forceinline__ void rope_pair(int row, int c, const float2 xv,
                                          float scale, float& y0, float& y1) {
    const int dd = c & 63;
    const int f0 = (dd < 32) ? dd : dd - 32;
    const int f1 = (dd + 1 < 32) ? dd + 1 : dd - 31;
    const float th0 = powf(10000.f, -(float)f0 * (1.f / 32.f));
    const float th1 = powf(10000.f, -(float)f1 * (1.f / 32.f));
    const float pos = (float)row;
    const float a0 = pos * th0;
    const float a1 = pos * th1;
    y0 = (xv.x * cosf(a0) - xv.y * sinf(a0)) * scale;
    y1 = (xv.y * cosf(a1) + xv.x * sinf(a1)) * scale;
}

// in-place fp32 (for k)
__global__ void rope_kernel(float* __restrict__ t, int ld, float scale) {
    const int idx = blockIdx.x * blockDim.x + threadIdx.x;
    const int row = idx >> 9;
    const int c   = (idx & 511) * 2;
    float2* p = reinterpret_cast<float2*>(t + (long)row * ld + c);
    float y0, y1;
    rope_pair(row, c, *p, scale, y0, y1);
    float2 out; out.x = y0; out.y = y1;
    *p = out;
}

// read fp32 -> write split bf16 (for q)
__global__ void rope_split_kernel(const float* __restrict__ src, int ld, float scale,
                                  __nv_bfloat16* __restrict__ hi,
                                  __nv_bfloat16* __restrict__ lo) {
    const int idx = blockIdx.x * blockDim.x + threadIdx.x;
    const int row = idx >> 9;
    const int c   = (idx & 511) * 2;
    const float2 xv = *reinterpret_cast<const float2*>(src + (long)row * ld + c);
    float y0, y1;
    rope_pair(row, c, xv, scale, y0, y1);
    uint32_t h, l;
    split2(y0, y1, h, l);
    *(uint32_t*)&hi[(long)row * DIM + c] = h;
    *(uint32_t*)&lo[(long)row * DIM + c] = l;
}

// split v fp32 -> bf16 hi/lo
__global__ void split_kernel(const float* __restrict__ src, int ld,
                             __nv_bfloat16* __restrict__ hi,
                             __nv_bfloat16* __restrict__ lo) {
    const int idx = blockIdx.x * blockDim.x + threadIdx.x;  // pairs
    const int row = idx >> 9;
    const int c   = (idx & 511) * 2;
    const float2 xv = *reinterpret_cast<const float2*>(src + (long)row * ld + c);
    uint32_t h, l;
    split2(xv.x, xv.y, h, l);
    *(uint32_t*)&hi[(long)row * DIM + c] = h;
    *(uint32_t*)&lo[(long)row * DIM + c] = l;
}

// ---------------- bilinear: kt[h][e][n] = sum_d k[n, h*64+d] * Wb[h,d,e], split output ----------------
__global__ void bilinear_kernel(const float* __restrict__ k, int ldk,
                                const float* __restrict__ Wb,
                                __nv_bfloat16* __restrict__ kthi,
                                __nv_bfloat16* __restrict__ ktlo) {
    const int h = blockIdx.y;
    const int rowbase = blockIdx.x * 64;
    __shared__ float Wbs[64][64];
    __shared__ float ks[64][65];
    for (int p = threadIdx.x; p < 64 * 64; p += 256) {
        const int r = p / 64, dd = p % 64;
        Wbs[r][dd] = Wb[h * 4096 + p];
        ks[r][dd]  = k[(long)(rowbase + r) * ldk + h * 64 + dd];
    }
    __syncthreads();
    for (int p = threadIdx.x; p < 64 * 64; p += 256) {
        const int e = p / 64, r = p % 64;
        float s = 0.f;
#pragma unroll
        for (int dd = 0; dd < 64; dd++) s = fmaf(ks[r][dd], Wbs[dd][e], s);
        const long o = ((long)h * 64 + e) * NTOK + rowbase + r;
        const __nv_bfloat16 bh = __float2bfloat16_rn(s);
        kthi[o] = bh;
        ktlo[o] = __float2bfloat16_rn(s - __bfloat162float(bh));
    }
}

// ---------------- tensor-core flash attention ----------------
// grid (NTOK/128, NHEADS), 256 threads (8 warps). Warp w owns rows 16w..16w+15.
#define SSTR 72
__global__ __launch_bounds__(256)
void flash_mma(const __nv_bfloat16* __restrict__ qhi,
               const __nv_bfloat16* __restrict__ qlo,
               const __nv_bfloat16* __restrict__ kthi,
               const __nv_bfloat16* __restrict__ ktlo,
               const __nv_bfloat16* __restrict__ vhi,
               const __nv_bfloat16* __restrict__ vlo,
               float* __restrict__ ao) {
    __shared__ __align__(16) __nv_bfloat16 H[128 * SSTR];
    __shared__ __align__(16) __nv_bfloat16 L[128 * SSTR];

    const int h     = blockIdx.y;
    const int qbase = blockIdx.x * 128;
    const int tid   = threadIdx.x;
    const int lane  = tid & 31;
    const int w     = tid >> 5;
    const int g     = lane >> 3;
    const int ri    = lane & 7;

    // ---- stage Q tile (128x64) hi/lo into smem ----
    for (int p = tid; p < 128 * 8; p += 256) {
        const int i = p >> 3, ec = (p & 7) * 8;
        const long go = (long)(qbase + i) * DIM + h * 64 + ec;
        *(uint4*)&H[i * SSTR + ec] = *(const uint4*)&qhi[go];
        *(uint4*)&L[i * SSTR + ec] = *(const uint4*)&qlo[go];
    }
    __syncthreads();

    // ---- extract Q frags (kept in registers for whole kernel) ----
    uint32_t aq_hi[4][4], aq_lo[4][4];
    {
        const int row = w * 16 + (g & 1) * 8 + ri;
#pragma unroll
        for (int kc = 0; kc < 4; kc++) {
            const int colb = (kc * 16 + (g >> 1) * 8) * 2;
            LDSM4(aq_hi[kc], s2u(H) + row * (SSTR * 2) + colb);
            LDSM4(aq_lo[kc], s2u(L) + row * (SSTR * 2) + colb);
        }
    }

    float o[8][4];
    float m0 = -3.4e38f, m1 = -3.4e38f, l0 = 0.f, l1 = 0.f;
#pragma unroll
    for (int t = 0; t < 8; t++)
#pragma unroll
        for (int r = 0; r < 4; r++) o[t][r] = 0.f;

    for (int j0 = 0; j0 < NTOK; j0 += 64) {
        __syncthreads();
        // ---- load Kt chunk [e][j] hi/lo ----
        for (int p = tid; p < 64 * 8; p += 256) {
            const int e = p >> 3, jc = (p & 7) * 8;
            const long go = ((long)h * 64 + e) * NTOK + j0 + jc;
            *(uint4*)&H[e * SSTR + jc] = *(const uint4*)&kthi[go];
            *(uint4*)&L[e * SSTR + jc] = *(const uint4*)&ktlo[go];
        }
        __syncthreads();

        // ---- S = Q @ Kt (3-product) ----
        float s[8][4];
#pragma unroll
        for (int t = 0; t < 8; t++)
#pragma unroll
            for (int r = 0; r < 4; r++) s[t][r] = 0.f;
#pragma unroll
        for (int kc = 0; kc < 4; kc++) {
            const int krow = kc * 16 + (g & 1) * 8 + ri;
#pragma unroll
            for (int ng = 0; ng < 4; ng++) {
                uint32_t bh[4], bl[4];
                const int colb = (ng * 16 + (g >> 1) * 8) * 2;
                LDSM4T(bh, s2u(H) + krow * (SSTR * 2) + colb);
                LDSM4T(bl, s2u(L) + krow * (SSTR * 2) + colb);
                MMA_BF16(s[2 * ng],     aq_hi[kc], bh);
                MMA_BF16(s[2 * ng],     aq_hi[kc], bl);
                MMA_BF16(s[2 * ng],     aq_lo[kc], bh);
                MMA_BF16(s[2 * ng + 1], aq_hi[kc], bh + 2);
                MMA_BF16(s[2 * ng + 1], aq_hi[kc], bl + 2);
                MMA_BF16(s[2 * ng + 1], aq_lo[kc], bh + 2);
            }
        }

        // ---- online softmax (rows r=lane>>2 half0, r+8 half1) ----
        float mx0 = -3.4e38f, mx1 = -3.4e38f;
#pragma unroll
        for (int t = 0; t < 8; t++) {
            mx0 = fmaxf(mx0, fmaxf(s[t][0], s[t][1]));
            mx1 = fmaxf(mx1, fmaxf(s[t][2], s[t][3]));
        }
        mx0 = fmaxf(mx0, __shfl_xor_sync(0xffffffffu, mx0, 1));
        mx0 = fmaxf(mx0, __shfl_xor_sync(0xffffffffu, mx0, 2));
        mx1 = fmaxf(mx1, __shfl_xor_sync(0xffffffffu, mx1, 1));
        mx1 = fmaxf(mx1, __shfl_xor_sync(0xffffffffu, mx1, 2));
        const float mn0 = fmaxf(m0, mx0);
        const float mn1 = fmaxf(m1, mx1);
        const float c0  = __expf(m0 - mn0);
        const float c1  = __expf(m1 - mn1);
        m0 = mn0; m1 = mn1;
        float rs0 = 0.f, rs1 = 0.f;
#pragma unroll
        for (int t = 0; t < 8; t++) {
            s[t][0] = __expf(s[t][0] - mn0);
            s[t][1] = __expf(s[t][1] - mn0);
            s[t][2] = __expf(s[t][2] - mn1);
            s[t][3] = __expf(s[t][3] - mn1);
            rs0 += s[t][0] + s[t][1];
            rs1 += s[t][2] + s[t][3];
        }
        rs0 += __shfl_xor_sync(0xffffffffu, rs0, 1);
        rs0 += __shfl_xor_sync(0xffffffffu, rs0, 2);
        rs1 += __shfl_xor_sync(0xffffffffu, rs1, 1);
        rs1 += __shfl_xor_sync(0xffffffffu, rs1, 2);
        l0 = l0 * c0 + rs0;
        l1 = l1 * c1 + rs1;
#pragma unroll
        for (int t = 0; t < 8; t++) {
            o[t][0] *= c0; o[t][1] *= c0;
            o[t][2] *= c1; o[t][3] *= c1;
        }

        // ---- build P frags (register-direct: C layout == A layout) ----
        uint32_t ap_hi[4][4], ap_lo[4][4];
#pragma unroll
        for (int c = 0; c < 4; c++) {
            split2(s[2 * c][0],     s[2 * c][1],     ap_hi[c][0], ap_lo[c][0]);
            split2(s[2 * c][2],     s[2 * c][3],     ap_hi[c][1], ap_lo[c][1]);
            split2(s[2 * c + 1][0], s[2 * c + 1][1], ap_hi[c][2], ap_lo[c][2]);
            split2(s[2 * c + 1][2], s[2 * c + 1][3], ap_hi[c][3], ap_lo[c][3]);
        }

        __syncthreads();
        // ---- load V chunk [j][e] hi/lo ----
        for (int p = tid; p < 64 * 8; p += 256) {
            const int j = p >> 3, ec = (p & 7) * 8;
            const long go = (long)(j0 + j) * DIM + h * 64 + ec;
            *(uint4*)&H[j * SSTR + ec] = *(const uint4*)&vhi[go];
            *(uint4*)&L[j * SSTR + ec] = *(const uint4*)&vlo[go];
        }
        __syncthreads();

        // ---- O += P @ V (3-product) ----
#pragma unroll
        for (int kc = 0; kc < 4; kc++) {
            const int krow = kc * 16 + (g & 1) * 8 + ri;
#pragma unroll
            for (int ng = 0; ng < 4; ng++) {
                uint32_t bh[4], bl[4];
                const int colb = (ng * 16 + (g >> 1) * 8) * 2;
                LDSM4T(bh, s2u(H) + krow * (SSTR * 2) + colb);
                LDSM4T(bl, s2u(L) + krow * (SSTR * 2) + colb);
                MMA_BF16(o[2 * ng],     ap_hi[kc], bh);
                MMA_BF16(o[2 * ng],     ap_hi[kc], bl);
                MMA_BF16(o[2 * ng],     ap_lo[kc], bh);
                MMA_BF16(o[2 * ng + 1], ap_hi[kc], bh + 2);
                MMA_BF16(o[2 * ng + 1], ap_hi[kc], bl + 2);
                MMA_BF16(o[2 * ng + 1], ap_lo[kc], bh + 2);
            }
        }
    }

    // ---- epilogue: normalize + store fp32 ----
    const float i0 = 1.f / l0;
    const float i1 = 1.f / l1;
    const int r  = qbase + w * 16 + (lane >> 2);
#pragma unroll
    for (int t = 0; t < 8; t++) {
        const int cc = h * 64 + t * 8 + (lane & 3) * 2;
        float2 t0, t1;
        t0.x = o[t][0] * i0; t0.y = o[t][1] * i0;
        t1.x = o[t][2] * i1; t1.y = o[t][3] * i1;
        *reinterpret_cast<float2*>(ao + (long)r * DIM + cc)       = t0;
        *reinterpret_cast<float2*>(ao + (long)(r + 8) * DIM + cc) = t1;
    }
}

// ---------------- launch ----------------
extern "C" void kernel_launch(void* const* d_in, const int* in_sizes, int n_in,
                              void* d_out, int out_size) {
    const float* x     = (const float*)d_in[0];
    const float* gamma = (const float*)d_in[1];
    const float* Wq    = (const float*)d_in[2];
    const float* Wkv   = (const float*)d_in[3];
    const float* Wb    = (const float*)d_in[4];
    const float* Wo    = (const float*)d_in[5];
    float* out = (float*)d_out;

    float *xn, *qkv, *ao;
    __nv_bfloat16 *q_hi, *q_lo, *kt_hi, *kt_lo, *v_hi, *v_lo;
    cudaGetSymbolAddress((void**)&xn,    g_xn);
    cudaGetSymbolAddress((void**)&qkv,   g_qkv);
    cudaGetSymbolAddress((void**)&ao,    g_ao);
    cudaGetSymbolAddress((void**)&q_hi,  g_q_hi);
    cudaGetSymbolAddress((void**)&q_lo,  g_q_lo);
    cudaGetSymbolAddress((void**)&kt_hi, g_kt_hi);
    cudaGetSymbolAddress((void**)&kt_lo, g_kt_lo);
    cudaGetSymbolAddress((void**)&v_hi,  g_v_hi);
    cudaGetSymbolAddress((void**)&v_lo,  g_v_lo);

    float* q = qkv;
    float* k = qkv + DIM;
    float* v = qkv + 2 * DIM;

    // 1. LayerNorm
    ln_kernel<<<NTOK, 256>>>(x, gamma, xn);

    // 2. qkv = xn @ [Wq | Wkv]
    {
        dim3 g(QKV_LD / 128, NTOK / 128, 1);
        gemm_bf16x3<<<g, 256>>>(xn, Wq, Wkv, qkv,
                                DIM, DIM, DIM, 2 * DIM, QKV_LD, DIM);
    }

    // 3. RoPE: q -> split bf16 (scale folded); k in-place fp32; v -> split bf16
    rope_split_kernel<<<NTOK * 512 / 256, 256>>>(q, QKV_LD, 0.125f, q_hi, q_lo);
    rope_kernel<<<NTOK * 512 / 256, 256>>>(k, QKV_LD, 1.0f);
    split_kernel<<<NTOK * 512 / 256, 256>>>(v, QKV_LD, v_hi, v_lo);

    // 4. bilinear K transform -> kt hi/lo [h][e][n]
    bilinear_kernel<<<dim3(NTOK / 64, NHEADS), 256>>>(k, QKV_LD, Wb, kt_hi, kt_lo);

    // 5-7. tensor-core flash attention
    flash_mma<<<dim3(NTOK / 128, NHEADS), 256>>>(
        q_hi, q_lo, kt_hi, kt_lo, v_hi, v_lo, ao);

    // 8. out = ao @ Wo
    {
        dim3 g(DIM / 128, NTOK / 128, 1);
        gemm_bf16x3<<<g, 256>>>(ao, Wo, Wo, out,
                                DIM, DIM, DIM, DIM, DIM, 1 << 30);
    }
}

// round 8
// speedup vs baseline: 2.8955x; 1.2700x over previous
#include <cuda_runtime.h>
#include <cuda_bf16.h>
#include <math.h>
#include <stdint.h>

#define NTOK   2048
#define DIM    1024
#define NHEADS 16
#define DHEAD  64
#define QKV_LD 3072

// ---------------- scratch (no allocations allowed) ----------------
__device__ float g_qkv [NTOK * QKV_LD];          // q | k | v (fp32, GEMM output)
__device__ __nv_bfloat16 g_xn_hi[NTOK * DIM];
__device__ __nv_bfloat16 g_xn_lo[NTOK * DIM];
__device__ __nv_bfloat16 g_wqkv_hi[DIM * QKV_LD];
__device__ __nv_bfloat16 g_wqkv_lo[DIM * QKV_LD];
__device__ __nv_bfloat16 g_wo_hi[DIM * DIM];
__device__ __nv_bfloat16 g_wo_lo[DIM * DIM];
__device__ __nv_bfloat16 g_q_hi [NTOK * DIM];
__device__ __nv_bfloat16 g_q_lo [NTOK * DIM];
__device__ __nv_bfloat16 g_kt_hi[NHEADS * DHEAD * NTOK];  // [h][e][n]
__device__ __nv_bfloat16 g_kt_lo[NHEADS * DHEAD * NTOK];
__device__ __nv_bfloat16 g_v_hi [NTOK * DIM];
__device__ __nv_bfloat16 g_v_lo [NTOK * DIM];
__device__ __nv_bfloat16 g_ao_hi[NTOK * DIM];
__device__ __nv_bfloat16 g_ao_lo[NTOK * DIM];

static __device__ __forceinline__ uint32_t s2u(const void* p) {
    return (uint32_t)__cvta_generic_to_shared(p);
}

#define LDSM4(R, addr) \
    asm volatile("ldmatrix.sync.aligned.m8n8.x4.shared.b16 {%0,%1,%2,%3},[%4];" \
        : "=r"((R)[0]), "=r"((R)[1]), "=r"((R)[2]), "=r"((R)[3]) : "r"(addr))
#define LDSM4T(R, addr) \
    asm volatile("ldmatrix.sync.aligned.m8n8.x4.trans.shared.b16 {%0,%1,%2,%3},[%4];" \
        : "=r"((R)[0]), "=r"((R)[1]), "=r"((R)[2]), "=r"((R)[3]) : "r"(addr))
#define MMA_BF16(D, A, B) \
    asm volatile("mma.sync.aligned.m16n8k16.row.col.f32.bf16.bf16.f32 " \
        "{%0,%1,%2,%3},{%4,%5,%6,%7},{%8,%9},{%0,%1,%2,%3};" \
        : "+f"((D)[0]), "+f"((D)[1]), "+f"((D)[2]), "+f"((D)[3]) \
        : "r"((A)[0]), "r"((A)[1]), "r"((A)[2]), "r"((A)[3]), "r"((B)[0]), "r"((B)[1]))
#define CP16(dst, src) \
    asm volatile("cp.async.ca.shared.global [%0],[%1],16;" :: "r"(dst), "l"(src))
#define CPCOMMIT() asm volatile("cp.async.commit_group;")
#define CPWAIT(n)  asm volatile("cp.async.wait_group %0;" :: "n"(n))

static __device__ __forceinline__ void split2(float x, float y,
                                              uint32_t& hi, uint32_t& lo) {
    float2 f; f.x = x; f.y = y;
    __nv_bfloat162 h = __float22bfloat162_rn(f);
    float2 hf = __bfloat1622float2(h);
    float2 r; r.x = x - hf.x; r.y = y - hf.y;
    __nv_bfloat162 l = __float22bfloat162_rn(r);
    hi = *(uint32_t*)&h; lo = *(uint32_t*)&l;
}

// ---------------- LayerNorm -> split bf16 ----------------
__global__ void ln_kernel(const float* __restrict__ x,
                          const float* __restrict__ gamma,
                          __nv_bfloat16* __restrict__ xhi,
                          __nv_bfloat16* __restrict__ xlo) {
    __shared__ float red[16];
    const int row = blockIdx.x;
    const float2* xr = reinterpret_cast<const float2*>(x + (long)row * DIM);
    float2 v[2];
    float s = 0.f, ss = 0.f;
#pragma unroll
    for (int i = 0; i < 2; i++) {
        v[i] = xr[threadIdx.x + i * 256];
        s += v[i].x + v[i].y;
        ss += v[i].x * v[i].x + v[i].y * v[i].y;
    }
#pragma unroll
    for (int o = 16; o > 0; o >>= 1) {
        s  += __shfl_xor_sync(0xffffffffu, s,  o);
        ss += __shfl_xor_sync(0xffffffffu, ss, o);
    }
    if ((threadIdx.x & 31) == 0) {
        red[threadIdx.x >> 5]       = s;
        red[8 + (threadIdx.x >> 5)] = ss;
    }
    __syncthreads();
    s = red[0]; ss = red[8];
#pragma unroll
    for (int i = 1; i < 8; i++) { s += red[i]; ss += red[8 + i]; }
    const float mu  = s * (1.f / DIM);
    const float var = ss * (1.f / DIM) - mu * mu;
    const float inv = rsqrtf(var + 1e-5f);
    const float2* g2 = reinterpret_cast<const float2*>(gamma);
#pragma unroll
    for (int i = 0; i < 2; i++) {
        const int p = threadIdx.x + i * 256;          // float2 index in [0,512)
        const float2 gg = g2[p];
        const float y0 = (v[i].x - mu) * inv * gg.x;
        const float y1 = (v[i].y - mu) * inv * gg.y;
        uint32_t h, l;
        split2(y0, y1, h, l);
        *(uint32_t*)&xhi[(long)row * DIM + 2 * p] = h;
        *(uint32_t*)&xlo[(long)row * DIM + 2 * p] = l;
    }
}

// ---------------- weight split: [Wq | Wkv] -> combined [1024][3072] hi/lo ----------------
__global__ void wsplit_qkv(const float* __restrict__ Wq,
                           const float* __restrict__ Wkv,
                           __nv_bfloat16* __restrict__ hi,
                           __nv_bfloat16* __restrict__ lo) {
    const int r = blockIdx.y;
    const int c = (blockIdx.x * blockDim.x + threadIdx.x) * 2;
    float2 v;
    if (c < DIM) v = *reinterpret_cast<const float2*>(Wq + (long)r * DIM + c);
    else         v = *reinterpret_cast<const float2*>(Wkv + (long)r * 2 * DIM + (c - DIM));
    uint32_t h, l;
    split2(v.x, v.y, h, l);
    *(uint32_t*)&hi[(long)r * QKV_LD + c] = h;
    *(uint32_t*)&lo[(long)r * QKV_LD + c] = l;
}

// ---------------- generic split: 1024 cols, fp32(lds) -> bf16 hi/lo (ldd) ----------------
__global__ void split_kernel(const float* __restrict__ src, int lds,
                             __nv_bfloat16* __restrict__ hi,
                             __nv_bfloat16* __restrict__ lo, int ldd) {
    const int idx = blockIdx.x * blockDim.x + threadIdx.x;  // pairs
    const int row = idx >> 9;
    const int c   = (idx & 511) * 2;
    const float2 xv = *reinterpret_cast<const float2*>(src + (long)row * lds + c);
    uint32_t h, l;
    split2(xv.x, xv.y, h, l);
    *(uint32_t*)&hi[(long)row * ldd + c] = h;
    *(uint32_t*)&lo[(long)row * ldd + c] = l;
}

// ---------------- pure-bf16 3-product GEMM, cp.async double-buffered ----------------
#define GA_ELE 5120   // 128*40
#define GB_ELE 4352   // 32*136
#define GSTAGE (2 * GA_ELE + 2 * GB_ELE)

__global__ __launch_bounds__(256)
void gemm_bf16p(const __nv_bfloat16* __restrict__ Ahi,
                const __nv_bfloat16* __restrict__ Alo,
                const __nv_bfloat16* __restrict__ Bhi,
                const __nv_bfloat16* __restrict__ Blo,
                float* __restrict__ C,
                int K, int lda, int ldb, int ldc) {
    extern __shared__ __align__(16) __nv_bfloat16 gsm[];

    const int tid  = threadIdx.x;
    const int lane = tid & 31;
    const int wid  = tid >> 5;
    const int wm   = wid >> 2;
    const int wn   = wid & 3;
    const int brow = blockIdx.y * 128;
    const int bcol = blockIdx.x * 128;

    float d[4][4][4];
#pragma unroll
    for (int i = 0; i < 4; i++)
#pragma unroll
        for (int j = 0; j < 4; j++)
#pragma unroll
            for (int r = 0; r < 4; r++) d[i][j][r] = 0.f;

    const int niter = K / 32;

    auto load_stage = [&](int kt, int st) {
        __nv_bfloat16* As_hi = gsm + st * GSTAGE;
        __nv_bfloat16* As_lo = As_hi + GA_ELE;
        __nv_bfloat16* Bs_hi = As_lo + GA_ELE;
        __nv_bfloat16* Bs_lo = Bs_hi + GB_ELE;
        const int k0 = kt * 32;
#pragma unroll
        for (int t = 0; t < 2; t++) {
            const int p  = tid + t * 256;
            const int ar = p >> 2, ac = (p & 3) * 8;
            CP16(s2u(As_hi + ar * 40 + ac), Ahi + (long)(brow + ar) * lda + k0 + ac);
            CP16(s2u(As_lo + ar * 40 + ac), Alo + (long)(brow + ar) * lda + k0 + ac);
            const int br = p >> 4, bc = (p & 15) * 8;
            CP16(s2u(Bs_hi + br * 136 + bc), Bhi + (long)(k0 + br) * ldb + bcol + bc);
            CP16(s2u(Bs_lo + br * 136 + bc), Blo + (long)(k0 + br) * ldb + bcol + bc);
        }
    };

    load_stage(0, 0);
    CPCOMMIT();

    for (int kt = 0; kt < niter; kt++) {
        if (kt + 1 < niter) {
            load_stage(kt + 1, (kt + 1) & 1);
            CPCOMMIT();
            CPWAIT(1);
        } else {
            CPWAIT(0);
        }
        __syncthreads();

        const __nv_bfloat16* As_hi = gsm + (kt & 1) * GSTAGE;
        const __nv_bfloat16* As_lo = As_hi + GA_ELE;
        const __nv_bfloat16* Bs_hi = As_lo + GA_ELE;
        const __nv_bfloat16* Bs_lo = Bs_hi + GB_ELE;
        const int g  = lane >> 3;
        const int ri = lane & 7;

#pragma unroll
        for (int kk = 0; kk < 32; kk += 16) {
            uint32_t a_hi[4][4], a_lo[4][4], b_hi[2][4], b_lo[2][4];
#pragma unroll
            for (int mi = 0; mi < 4; mi++) {
                const int row   = wm * 64 + mi * 16 + (g & 1) * 8 + ri;
                const int chunk = (kk >> 3) + (g >> 1);
                LDSM4(a_hi[mi], s2u(As_hi) + row * 80 + chunk * 16);
                LDSM4(a_lo[mi], s2u(As_lo) + row * 80 + chunk * 16);
            }
#pragma unroll
            for (int nj2 = 0; nj2 < 2; nj2++) {
                const int krow = kk + (g & 1) * 8 + ri;
                const int col  = wn * 32 + nj2 * 16 + (g >> 1) * 8;
                LDSM4T(b_hi[nj2], s2u(Bs_hi) + krow * 272 + col * 2);
                LDSM4T(b_lo[nj2], s2u(Bs_lo) + krow * 272 + col * 2);
            }
#pragma unroll
            for (int mi = 0; mi < 4; mi++)
#pragma unroll
                for (int nj = 0; nj < 4; nj++) {
                    const int nj2 = nj >> 1, u = (nj & 1) * 2;
                    MMA_BF16(d[mi][nj], a_hi[mi], b_hi[nj2] + u);
                    MMA_BF16(d[mi][nj], a_hi[mi], b_lo[nj2] + u);
                    MMA_BF16(d[mi][nj], a_lo[mi], b_hi[nj2] + u);
                }
        }
        __syncthreads();
    }

#pragma unroll
    for (int mi = 0; mi < 4; mi++)
#pragma unroll
        for (int nj = 0; nj < 4; nj++) {
            const int r  = brow + wm * 64 + mi * 16 + (lane >> 2);
            const int cc = bcol + wn * 32 + nj * 8 + (lane & 3) * 2;
            float2 t0, t1;
            t0.x = d[mi][nj][0]; t0.y = d[mi][nj][1];
            t1.x = d[mi][nj][2]; t1.y = d[mi][nj][3];
            *reinterpret_cast<float2*>(C + (long)r * ldc + cc)       = t0;
            *reinterpret_cast<float2*>(C + (long)(r + 8) * ldc + cc) = t1;
        }
}

// ---------------- RoPE ----------------
__device__ __forceinline__ void rope_pair(int row, int c, const float2 xv,
                                          float scale, float& y0, float& y1) {
    const int dd = c & 63;
    const int f0 = (dd < 32) ? dd : dd - 32;
    const int f1 = (dd + 1 < 32) ? dd + 1 : dd - 31;
    const float th0 = powf(10000.f, -(float)f0 * (1.f / 32.f));
    const float th1 = powf(10000.f, -(float)f1 * (1.f / 32.f));
    const float pos = (float)row;
    const float a0 = pos * th0;
    const float a1 = pos * th1;
    y0 = (xv.x * cosf(a0) - xv.y * sinf(a0)) * scale;
    y1 = (xv.y * cosf(a1) + xv.x * sinf(a1)) * scale;
}

__global__ void rope_kernel(float* __restrict__ t, int ld, float scale) {
    const int idx = blockIdx.x * blockDim.x + threadIdx.x;
    const int row = idx >> 9;
    const int c   = (idx & 511) * 2;
    float2* p = reinterpret_cast<float2*>(t + (long)row * ld + c);
    float y0, y1;
    rope_pair(row, c, *p, scale, y0, y1);
    float2 out; out.x = y0; out.y = y1;
    *p = out;
}

__global__ void rope_split_kernel(const float* __restrict__ src, int ld, float scale,
                                  __nv_bfloat16* __restrict__ hi,
                                  __nv_bfloat16* __restrict__ lo) {
    const int idx = blockIdx.x * blockDim.x + threadIdx.x;
    const int row = idx >> 9;
    const int c   = (idx & 511) * 2;
    const float2 xv = *reinterpret_cast<const float2*>(src + (long)row * ld + c);
    float y0, y1;
    rope_pair(row, c, xv, scale, y0, y1);
    uint32_t h, l;
    split2(y0, y1, h, l);
    *(uint32_t*)&hi[(long)row * DIM + c] = h;
    *(uint32_t*)&lo[(long)row * DIM + c] = l;
}

// ---------------- bilinear K transform, split output ----------------
__global__ void bilinear_kernel(const float* __restrict__ k, int ldk,
                                const float* __restrict__ Wb,
                                __nv_bfloat16* __restrict__ kthi,
                                __nv_bfloat16* __restrict__ ktlo) {
    const int h = blockIdx.y;
    const int rowbase = blockIdx.x * 64;
    __shared__ float Wbs[64][64];
    __shared__ float ks[64][65];
    for (int p = threadIdx.x; p < 64 * 64; p += 256) {
        const int r = p / 64, dd = p % 64;
        Wbs[r][dd] = Wb[h * 4096 + p];
        ks[r][dd]  = k[(long)(rowbase + r) * ldk + h * 64 + dd];
    }
    __syncthreads();
    for (int p = threadIdx.x; p < 64 * 64; p += 256) {
        const int e = p / 64, r = p % 64;
        float s = 0.f;
#pragma unroll
        for (int dd = 0; dd < 64; dd++) s = fmaf(ks[r][dd], Wbs[dd][e], s);
        const long o = ((long)h * 64 + e) * NTOK + rowbase + r;
        const __nv_bfloat16 bh = __float2bfloat16_rn(s);
        kthi[o] = bh;
        ktlo[o] = __float2bfloat16_rn(s - __bfloat162float(bh));
    }
}

// ---------------- tensor-core flash attention, cp.async double-buffered ----------------
#define FSTR   72
#define FCHUNK (64 * FSTR)
__global__ __launch_bounds__(256)
void flash_mma(const __nv_bfloat16* __restrict__ qhi,
               const __nv_bfloat16* __restrict__ qlo,
               const __nv_bfloat16* __restrict__ kthi,
               const __nv_bfloat16* __restrict__ ktlo,
               const __nv_bfloat16* __restrict__ vhi,
               const __nv_bfloat16* __restrict__ vlo,
               __nv_bfloat16* __restrict__ aohi,
               __nv_bfloat16* __restrict__ aolo) {
    extern __shared__ __align__(16) __nv_bfloat16 fsm[];
    __nv_bfloat16* KH = fsm;
    __nv_bfloat16* KL = fsm + 2 * FCHUNK;
    __nv_bfloat16* VH = fsm + 4 * FCHUNK;
    __nv_bfloat16* VL = fsm + 6 * FCHUNK;

    const int h     = blockIdx.y;
    const int qbase = blockIdx.x * 128;
    const int tid   = threadIdx.x;
    const int lane  = tid & 31;
    const int w     = tid >> 5;
    const int g     = lane >> 3;
    const int ri    = lane & 7;

    for (int p = tid; p < 128 * 8; p += 256) {
        const int i = p >> 3, ec = (p & 7) * 8;
        const long go = (long)(qbase + i) * DIM + h * 64 + ec;
        *(uint4*)&KH[i * FSTR + ec] = *(const uint4*)&qhi[go];
        *(uint4*)&KL[i * FSTR + ec] = *(const uint4*)&qlo[go];
    }
    __syncthreads();

    uint32_t aq_hi[4][4], aq_lo[4][4];
    {
        const int row = w * 16 + (g & 1) * 8 + ri;
#pragma unroll
        for (int kc = 0; kc < 4; kc++) {
            const int colb = (kc * 16 + (g >> 1) * 8) * 2;
            LDSM4(aq_hi[kc], s2u(KH) + row * (FSTR * 2) + colb);
            LDSM4(aq_lo[kc], s2u(KL) + row * (FSTR * 2) + colb);
        }
    }
    __syncthreads();

    auto load_kv = [&](int j0, int st) {
        __nv_bfloat16* kh = KH + st * FCHUNK;
        __nv_bfloat16* kl = KL + st * FCHUNK;
        __nv_bfloat16* vh = VH + st * FCHUNK;
        __nv_bfloat16* vl = VL + st * FCHUNK;
#pragma unroll
        for (int t = 0; t < 2; t++) {
            const int p = tid + t * 256;
            const int e = p >> 3, jc = (p & 7) * 8;
            CP16(s2u(kh + e * FSTR + jc), kthi + ((long)h * 64 + e) * NTOK + j0 + jc);
            CP16(s2u(kl + e * FSTR + jc), ktlo + ((long)h * 64 + e) * NTOK + j0 + jc);
            CP16(s2u(vh + e * FSTR + jc), vhi + (long)(j0 + e) * DIM + h * 64 + jc);
            CP16(s2u(vl + e * FSTR + jc), vlo + (long)(j0 + e) * DIM + h * 64 + jc);
        }
    };

    float o[8][4];
    float m0 = -3.4e38f, m1 = -3.4e38f, l0 = 0.f, l1 = 0.f;
#pragma unroll
    for (int t = 0; t < 8; t++)
#pragma unroll
        for (int r = 0; r < 4; r++) o[t][r] = 0.f;

    load_kv(0, 0);
    CPCOMMIT();

    for (int it = 0; it < NTOK / 64; it++) {
        if (it + 1 < NTOK / 64) {
            load_kv((it + 1) * 64, (it + 1) & 1);
            CPCOMMIT();
            CPWAIT(1);
        } else {
            CPWAIT(0);
        }
        __syncthreads();

        const __nv_bfloat16* kh = KH + (it & 1) * FCHUNK;
        const __nv_bfloat16* kl = KL + (it & 1) * FCHUNK;
        const __nv_bfloat16* vh = VH + (it & 1) * FCHUNK;
        const __nv_bfloat16* vl = VL + (it & 1) * FCHUNK;

        float s[8][4];
#pragma unroll
        for (int t = 0; t < 8; t++)
#pragma unroll
            for (int r = 0; r < 4; r++) s[t][r] = 0.f;
#pragma unroll
        for (int kc = 0; kc < 4; kc++) {
            const int krow = kc * 16 + (g & 1) * 8 + ri;
#pragma unroll
            for (int ng = 0; ng < 4; ng++) {
                uint32_t bh[4], bl[4];
                const int colb = (ng * 16 + (g >> 1) * 8) * 2;
                LDSM4T(bh, s2u(kh) + krow * (FSTR * 2) + colb);
                LDSM4T(bl, s2u(kl) + krow * (FSTR * 2) + colb);
                MMA_BF16(s[2 * ng],     aq_hi[kc], bh);
                MMA_BF16(s[2 * ng],     aq_hi[kc], bl);
                MMA_BF16(s[2 * ng],     aq_lo[kc], bh);
                MMA_BF16(s[2 * ng + 1], aq_hi[kc], bh + 2);
                MMA_BF16(s[2 * ng + 1], aq_hi[kc], bl + 2);
                MMA_BF16(s[2 * ng + 1], aq_lo[kc], bh + 2);
            }
        }

        float mx0 = -3.4e38f, mx1 = -3.4e38f;
#pragma unroll
        for (int t = 0; t < 8; t++) {
            mx0 = fmaxf(mx0, fmaxf(s[t][0], s[t][1]));
            mx1 = fmaxf(mx1, fmaxf(s[t][2], s[t][3]));
        }
        mx0 = fmaxf(mx0, __shfl_xor_sync(0xffffffffu, mx0, 1));
        mx0 = fmaxf(mx0, __shfl_xor_sync(0xffffffffu, mx0, 2));
        mx1 = fmaxf(mx1, __shfl_xor_sync(0xffffffffu, mx1, 1));
        mx1 = fmaxf(mx1, __shfl_xor_sync(0xffffffffu, mx1, 2));
        const float mn0 = fmaxf(m0, mx0);
        const float mn1 = fmaxf(m1, mx1);
        const float c0  = __expf(m0 - mn0);
        const float c1  = __expf(m1 - mn1);
        m0 = mn0; m1 = mn1;
        float rs0 = 0.f, rs1 = 0.f;
#pragma unroll
        for (int t = 0; t < 8; t++) {
            s[t][0] = __expf(s[t][0] - mn0);
            s[t][1] = __expf(s[t][1] - mn0);
            s[t][2] = __expf(s[t][2] - mn1);
            s[t][3] = __expf(s[t][3] - mn1);
            rs0 += s[t][0] + s[t][1];
            rs1 += s[t][2] + s[t][3];
        }
        rs0 += __shfl_xor_sync(0xffffffffu, rs0, 1);
        rs0 += __shfl_xor_sync(0xffffffffu, rs0, 2);
        rs1 += __shfl_xor_sync(0xffffffffu, rs1, 1);
        rs1 += __shfl_xor_sync(0xffffffffu, rs1, 2);
        l0 = l0 * c0 + rs0;
        l1 = l1 * c1 + rs1;
#pragma unroll
        for (int t = 0; t < 8; t++) {
            o[t][0] *= c0; o[t][1] *= c0;
            o[t][2] *= c1; o[t][3] *= c1;
        }

        uint32_t ap_hi[4][4], ap_lo[4][4];
#pragma unroll
        for (int c = 0; c < 4; c++) {
            split2(s[2 * c][0],     s[2 * c][1],     ap_hi[c][0], ap_lo[c][0]);
            split2(s[2 * c][2],     s[2 * c][3],     ap_hi[c][1], ap_lo[c][1]);
            split2(s[2 * c + 1][0], s[2 * c + 1][1], ap_hi[c][2], ap_lo[c][2]);
            split2(s[2 * c + 1][2], s[2 * c + 1][3], ap_hi[c][3], ap_lo[c][3]);
        }

#pragma unroll
        for (int kc = 0; kc < 4; kc++) {
            const int krow = kc * 16 + (g & 1) * 8 + ri;
#pragma unroll
            for (int ng = 0; ng < 4; ng++) {
                uint32_t bh[4], bl[4];
                const int colb = (ng * 16 + (g >> 1) * 8) * 2;
                LDSM4T(bh, s2u(vh) + krow * (FSTR * 2) + colb);
                LDSM4T(bl, s2u(vl) + krow * (FSTR * 2) + colb);
                MMA_BF16(o[2 * ng],     ap_hi[kc], bh);
                MMA_BF16(o[2 * ng],     ap_hi[kc], bl);
                MMA_BF16(o[2 * ng],     ap_lo[kc], bh);
                MMA_BF16(o[2 * ng + 1], ap_hi[kc], bh + 2);
                MMA_BF16(o[2 * ng + 1], ap_hi[kc], bl + 2);
                MMA_BF16(o[2 * ng + 1], ap_lo[kc], bh + 2);
            }
        }
        __syncthreads();
    }

    const float i0 = 1.f / l0;
    const float i1 = 1.f / l1;
    const int r  = qbase + w * 16 + (lane >> 2);
#pragma unroll
    for (int t = 0; t < 8; t++) {
        const int cc = h * 64 + t * 8 + (lane & 3) * 2;
        uint32_t h0, l0u, h1, l1u;
        split2(o[t][0] * i0, o[t][1] * i0, h0, l0u);
        split2(o[t][2] * i1, o[t][3] * i1, h1, l1u);
        *(uint32_t*)&aohi[(long)r * DIM + cc]       = h0;
        *(uint32_t*)&aolo[(long)r * DIM + cc]       = l0u;
        *(uint32_t*)&aohi[(long)(r + 8) * DIM + cc] = h1;
        *(uint32_t*)&aolo[(long)(r + 8) * DIM + cc] = l1u;
    }
}

// ---------------- launch ----------------
extern "C" void kernel_launch(void* const* d_in, const int* in_sizes, int n_in,
                              void* d_out, int out_size) {
    const float* x     = (const float*)d_in[0];
    const float* gamma = (const float*)d_in[1];
    const float* Wq    = (const float*)d_in[2];
    const float* Wkv   = (const float*)d_in[3];
    const float* Wb    = (const float*)d_in[4];
    const float* Wo    = (const float*)d_in[5];
    float* out = (float*)d_out;

    float* qkv;
    __nv_bfloat16 *xn_hi, *xn_lo, *wqkv_hi, *wqkv_lo, *wo_hi, *wo_lo;
    __nv_bfloat16 *q_hi, *q_lo, *kt_hi, *kt_lo, *v_hi, *v_lo, *ao_hi, *ao_lo;
    cudaGetSymbolAddress((void**)&qkv,     g_qkv);
    cudaGetSymbolAddress((void**)&xn_hi,   g_xn_hi);
    cudaGetSymbolAddress((void**)&xn_lo,   g_xn_lo);
    cudaGetSymbolAddress((void**)&wqkv_hi, g_wqkv_hi);
    cudaGetSymbolAddress((void**)&wqkv_lo, g_wqkv_lo);
    cudaGetSymbolAddress((void**)&wo_hi,   g_wo_hi);
    cudaGetSymbolAddress((void**)&wo_lo,   g_wo_lo);
    cudaGetSymbolAddress((void**)&q_hi,    g_q_hi);
    cudaGetSymbolAddress((void**)&q_lo,    g_q_lo);
    cudaGetSymbolAddress((void**)&kt_hi,   g_kt_hi);
    cudaGetSymbolAddress((void**)&kt_lo,   g_kt_lo);
    cudaGetSymbolAddress((void**)&v_hi,    g_v_hi);
    cudaGetSymbolAddress((void**)&v_lo,    g_v_lo);
    cudaGetSymbolAddress((void**)&ao_hi,   g_ao_hi);
    cudaGetSymbolAddress((void**)&ao_lo,   g_ao_lo);

    float* k = qkv + DIM;
    float* q = qkv;
    float* v = qkv + 2 * DIM;

    const int gemm_smem = GSTAGE * 2 * (int)sizeof(__nv_bfloat16);
    const int flash_smem = 8 * FCHUNK * (int)sizeof(__nv_bfloat16);
    cudaFuncSetAttribute(gemm_bf16p,
                         cudaFuncAttributeMaxDynamicSharedMemorySize, gemm_smem);
    cudaFuncSetAttribute(flash_mma,
                         cudaFuncAttributeMaxDynamicSharedMemorySize, flash_smem);

    // 1. LayerNorm -> split bf16
    ln_kernel<<<NTOK, 256>>>(x, gamma, xn_hi, xn_lo);

    // 1b. weight splits (independent)
    wsplit_qkv<<<dim3(QKV_LD / 512, DIM), 256>>>(Wq, Wkv, wqkv_hi, wqkv_lo);
    split_kernel<<<DIM * 512 / 256, 256>>>(Wo, DIM, wo_hi, wo_lo, DIM);

    // 2. qkv = xn @ [Wq | Wkv]
    gemm_bf16p<<<dim3(QKV_LD / 128, NTOK / 128), 256, gemm_smem>>>(
        xn_hi, xn_lo, wqkv_hi, wqkv_lo, qkv, DIM, DIM, QKV_LD, QKV_LD);

    // 3. RoPE: q -> split bf16 (scale folded); k in-place fp32; v -> split bf16
    rope_split_kernel<<<NTOK * 512 / 256, 256>>>(q, QKV_LD, 0.125f, q_hi, q_lo);
    rope_kernel<<<NTOK * 512 / 256, 256>>>(k, QKV_LD, 1.0f);
    split_kernel<<<NTOK * 512 / 256, 256>>>(v, QKV_LD, v_hi, v_lo, DIM);

    // 4. bilinear K transform -> kt hi/lo [h][e][n]
    bilinear_kernel<<<dim3(NTOK / 64, NHEADS), 256>>>(k, QKV_LD, Wb, kt_hi, kt_lo);

    // 5-7. flash attention -> ao split bf16
    flash_mma<<<dim3(NTOK / 128, NHEADS), 256, flash_smem>>>(
        q_hi, q_lo, kt_hi, kt_lo, v_hi, v_lo, ao_hi, ao_lo);

    // 8. out = ao @ Wo
    gemm_bf16p<<<dim3(DIM / 128, NTOK / 128), 256, gemm_smem>>>(
        ao_hi, ao_lo, wo_hi, wo_lo, out, DIM, DIM, DIM, DIM);
}